// round 14
// baseline (speedup 1.0000x reference)
#include <cuda_runtime.h>
#include <cuda_bf16.h>
#include <math.h>
#include <stdint.h>

#define HID 1024
#define VOC 32000
#define MEMN 32
#define BAT 32
#define TN 64
#define RN (TN*BAT)      // 2048
#define G3 (3*HID)       // 3072
#define SLOT (BAT*HID)   // 32768
#define NBLK 128
#define WOUTB 128000     // (VOC*HID)/256 blocks for W_out conversion

// ---------------- device scratch (static, no allocs) ----------------
__device__ __align__(16) __nv_bfloat16 g_Wout[(size_t)VOC*HID];
__device__ __align__(16) __nv_bfloat16 g_Wih3[(size_t)G3*HID];   // bf16, rows permuted 3*h+g
__device__ __align__(16) float g_Whh3f[(size_t)G3*HID];          // f32, rows permuted 3*h+g
__device__ __align__(16) float g_bih3[G3];
__device__ __align__(16) float g_bhh3[G3];
__device__ __align__(16) __nv_bfloat16 g_Wp1[(size_t)HID*HID];   // bf16 x-half of W_proj
__device__ __align__(16) float g_Wp2f[(size_t)HID*HID];          // f32 mem-half of W_proj
__device__ __align__(16) __nv_bfloat16 g_xbf[(size_t)RN*HID];    // relu(emb), rows (t*B+b)
__device__ __align__(16) float         g_S  [(size_t)(MEMN+TN)*SLOT];  // state ring f32
__device__ __align__(16) __nv_bfloat16 g_Sbf[(size_t)(MEMN+TN)*SLOT];  // state ring bf16
__device__ __align__(16) float g_giAll[(size_t)RN*G3];           // x@W_ih^T+b_ih (perm cols)
__device__ __align__(16) float g_projA[(size_t)RN*HID];          // x@Wp1^T+b_proj
__device__ __align__(16) float g_proj[(size_t)BAT*HID];
__device__ __align__(16) float g_sel[(size_t)BAT*HID];
__device__ __align__(16) float g_logits[(size_t)RN*VOC];
__device__ unsigned g_barCnt;

// ---------------- helpers ----------------
__device__ __forceinline__ unsigned su32(const void* p) {
    return (unsigned)__cvta_generic_to_shared(p);
}
__device__ __forceinline__ void cpa16(void* smem_dst, const void* gsrc) {
    asm volatile("cp.async.cg.shared.global [%0], [%1], 16;"
                 :: "r"(su32(smem_dst)), "l"(gsrc));
}
#define CPA_COMMIT() asm volatile("cp.async.commit_group;")
#define CPA_WAIT0()  asm volatile("cp.async.wait_group 0;" ::: "memory")

__device__ __forceinline__ void ldmx4(unsigned* r, unsigned a) {
    asm volatile("ldmatrix.sync.aligned.m8n8.x4.shared.b16 {%0,%1,%2,%3},[%4];"
                 : "=r"(r[0]), "=r"(r[1]), "=r"(r[2]), "=r"(r[3]) : "r"(a));
}
__device__ __forceinline__ void ldmx2(unsigned* r, unsigned a) {
    asm volatile("ldmatrix.sync.aligned.m8n8.x2.shared.b16 {%0,%1},[%2];"
                 : "=r"(r[0]), "=r"(r[1]) : "r"(a));
}
__device__ __forceinline__ void mma16816(float* c, const unsigned* a, const unsigned* b) {
    asm volatile(
        "mma.sync.aligned.m16n8k16.row.col.f32.bf16.bf16.f32 "
        "{%0,%1,%2,%3},{%4,%5,%6,%7},{%8,%9},{%0,%1,%2,%3};"
        : "+f"(c[0]), "+f"(c[1]), "+f"(c[2]), "+f"(c[3])
        : "r"(a[0]), "r"(a[1]), "r"(a[2]), "r"(a[3]), "r"(b[0]), "r"(b[1]));
}
__device__ __forceinline__ uint32_t f2tf(float f) {
    uint32_t r;
    asm("cvt.rna.tf32.f32 %0, %1;" : "=r"(r) : "f"(f));
    return r;
}
__device__ __forceinline__ void mma1688tf(float* c, const uint32_t* a, const uint32_t* b) {
    asm volatile(
        "mma.sync.aligned.m16n8k8.row.col.f32.tf32.tf32.f32 "
        "{%0,%1,%2,%3},{%4,%5,%6,%7},{%8,%9},{%0,%1,%2,%3};"
        : "+f"(c[0]), "+f"(c[1]), "+f"(c[2]), "+f"(c[3])
        : "r"(a[0]), "r"(a[1]), "r"(a[2]), "r"(a[3]), "r"(b[0]), "r"(b[1]));
}

// ---------------- grid barrier (monotonic counter) ----------------
__device__ __forceinline__ unsigned ldacq(const unsigned* p) {
    unsigned v;
    asm volatile("ld.acquire.gpu.global.u32 %0, [%1];" : "=r"(v) : "l"(p));
    return v;
}
__device__ __forceinline__ void gsync(unsigned &target) {
    __syncthreads();
    if (threadIdx.x == 0) {
        __threadfence();
        atomicAdd(&g_barCnt, 1u);
        target += NBLK;
        while (ldacq(&g_barCnt) < target) { }
    }
    __syncthreads();
}

// ---------------- prep kernels ----------------
__global__ void k_prepA(const float* __restrict__ W_out, const float* __restrict__ W_ih,
                        const float* __restrict__ W_hh, const float* __restrict__ W_proj,
                        const float* __restrict__ b_ih, const float* __restrict__ b_hh) {
    int blk = blockIdx.x, tid = threadIdx.x;
    if (blk < WOUTB) {
        size_t i = (size_t)blk * 256 + tid;
        g_Wout[i] = __float2bfloat16_rn(W_out[i]);
    } else if (blk < WOUTB + 12288) {
        int i = (blk - WOUTB) * 256 + tid;
        int srow = i >> 10, k = i & 1023;
        int g = srow >> 10, h = srow & 1023;
        g_Wih3[((size_t)(3*h + g) << 10) | k] = __float2bfloat16_rn(W_ih[i]);
    } else if (blk < WOUTB + 24576) {
        int i = (blk - WOUTB - 12288) * 256 + tid;
        int srow = i >> 10, k = i & 1023;
        int g = srow >> 10, h = srow & 1023;
        g_Whh3f[((size_t)(3*h + g) << 10) | k] = W_hh[i];
    } else if (blk < WOUTB + 24576 + 4096) {
        int i = (blk - WOUTB - 24576) * 256 + tid;
        int j = i >> 10, k = i & 1023;
        g_Wp1[i]  = __float2bfloat16_rn(W_proj[(size_t)j * 2048 + k]);
        g_Wp2f[i] = W_proj[(size_t)j * 2048 + 1024 + k];
    } else {
        int i = (blk - WOUTB - 24576 - 4096) * 256 + tid;
        if (i < G3) {
            int g = i >> 10, h = i & 1023;
            g_bih3[3*h + g] = b_ih[i];
            g_bhh3[3*h + g] = b_hh[i];
        }
    }
}
__global__ void k_prepB(const int* __restrict__ input, const float* __restrict__ emb,
                        const float* __restrict__ memory) {
    int blk = blockIdx.x, tid = threadIdx.x;
    if (blk == 0 && tid == 0) g_barCnt = 0;
    if (blk < 8192) {
        int idx = blk * 256 + tid;
        int r = idx >> 10, h = idx & 1023;
        int t = r >> 5, b = r & 31;
        int tok = input[b * TN + t];
        float v = emb[(size_t)tok * HID + h];
        g_xbf[idx] = __float2bfloat16_rn(v > 0.f ? v : 0.f);
    } else {
        int idx = (blk - 8192) * 256 + tid;
        int k = idx >> 15, rest = idx & 32767;
        float v = memory[(size_t)(31 - k) * SLOT + rest];
        g_S[idx] = v;
        g_Sbf[idx] = __float2bfloat16_rn(v);
    }
}

// ---------------- bf16 128x128 GEMM body, cp.async 2-stage (for gi/projA) ----------------
__device__ __forceinline__ void gemm_prefetch(
    const __nv_bfloat16* A, const __nv_bfloat16* Wt, int m0, int n0, int k0,
    __nv_bfloat16 (*As)[40], __nv_bfloat16 (*Bs)[40], int tid)
{
#pragma unroll
    for (int v = 0; v < 2; v++) {
        int task = tid + v * 256;
        int row = task >> 2, seg = task & 3;
        cpa16(&As[row][seg * 8], &A [(size_t)(m0 + row) * 1024 + k0 + seg * 8]);
        cpa16(&Bs[row][seg * 8], &Wt[(size_t)(n0 + row) * 1024 + k0 + seg * 8]);
    }
    CPA_COMMIT();
}

__device__ __forceinline__ void gemm128_body(
    const __nv_bfloat16* __restrict__ A, const __nv_bfloat16* __restrict__ Wt,
    const float* __restrict__ bias, float* __restrict__ C, int N, int m0, int n0,
    __nv_bfloat16 (*As2)[128][40], __nv_bfloat16 (*Bs2)[128][40])
{
    const int tid = threadIdx.x, lane = tid & 31, wid = tid >> 5;
    const int wm = (wid & 1) * 64;
    const int wn = (wid >> 1) * 32;
    float acc[4][4][4] = {};

    gemm_prefetch(A, Wt, m0, n0, 0, As2[0], Bs2[0], tid);
    for (int it = 0; it < 32; it++) {
        CPA_WAIT0();
        __syncthreads();
        if (it < 31)
            gemm_prefetch(A, Wt, m0, n0, (it + 1) * 32, As2[(it + 1) & 1], Bs2[(it + 1) & 1], tid);
        __nv_bfloat16 (*As)[40] = As2[it & 1];
        __nv_bfloat16 (*Bs)[40] = Bs2[it & 1];
#pragma unroll
        for (int kk = 0; kk < 32; kk += 16) {
            unsigned af[4][4], bfm[4][2];
#pragma unroll
            for (int mi = 0; mi < 4; mi++)
                ldmx4(af[mi], su32(&As[wm + mi * 16 + (lane & 15)][kk + (lane >> 4) * 8]));
#pragma unroll
            for (int ni = 0; ni < 4; ni++)
                ldmx2(bfm[ni], su32(&Bs[wn + ni * 8 + (lane & 7)][kk + ((lane >> 3) & 1) * 8]));
#pragma unroll
            for (int mi = 0; mi < 4; mi++)
#pragma unroll
                for (int ni = 0; ni < 4; ni++)
                    mma16816(acc[mi][ni], af[mi], bfm[ni]);
        }
    }
#pragma unroll
    for (int mi = 0; mi < 4; mi++)
#pragma unroll
        for (int ni = 0; ni < 4; ni++) {
            int row = m0 + wm + mi * 16 + (lane >> 2);
            int col = n0 + wn + ni * 8 + (lane & 3) * 2;
            float b0 = bias[col], b1 = bias[col + 1];
            C[(size_t)row * N + col]           = acc[mi][ni][0] + b0;
            C[(size_t)row * N + col + 1]       = acc[mi][ni][1] + b1;
            C[(size_t)(row + 8) * N + col]     = acc[mi][ni][2] + b0;
            C[(size_t)(row + 8) * N + col + 1] = acc[mi][ni][3] + b1;
        }
}

// gi (y<24) + projA (y>=24) in one launch
__global__ __launch_bounds__(256) void k_gemm_all(const float* __restrict__ b_proj)
{
    __shared__ __align__(16) __nv_bfloat16 As2[2][128][40];
    __shared__ __align__(16) __nv_bfloat16 Bs2[2][128][40];
    int m0 = blockIdx.x * 128;
    if (blockIdx.y < 24)
        gemm128_body(g_xbf, g_Wih3, g_bih3, g_giAll, G3, m0, blockIdx.y * 128, As2, Bs2);
    else
        gemm128_body(g_xbf, g_Wp1, b_proj, g_projA, HID, m0, (blockIdx.y - 24) * 128, As2, Bs2);
}

// ---------------- vocab GEMM: 128x256 tile, 512 threads, warp tile 64x32 ----------------
// 16 warps = 4 warps/SMSP for latency hiding. 2-stage cp.async, 61440 B dynamic smem.
#define VOC_STAGE (128*40 + 256*40)     // bf16 elements per stage (15360)

__device__ __forceinline__ void voc_prefetch(
    const __nv_bfloat16* A, int m0, int n0, int k0,
    __nv_bfloat16* As, __nv_bfloat16* Bs, int tid)
{
    {                                    // A: 128 rows x 4 segs = 512 tasks
        int row = tid >> 2, seg = tid & 3;
        cpa16(&As[row * 40 + seg * 8], &A[(size_t)(m0 + row) * 1024 + k0 + seg * 8]);
    }
#pragma unroll
    for (int v = 0; v < 2; v++) {        // B: 256 rows x 4 segs = 1024 tasks
        int task = tid + v * 512;
        int row = task >> 2, seg = task & 3;
        cpa16(&Bs[row * 40 + seg * 8], &g_Wout[(size_t)(n0 + row) * 1024 + k0 + seg * 8]);
    }
    CPA_COMMIT();
}

__global__ __launch_bounds__(512, 1) void k_voc(const float* __restrict__ b_out)
{
    extern __shared__ __align__(16) __nv_bfloat16 vsm[];
    __nv_bfloat16* As2[2] = { vsm, vsm + VOC_STAGE };
    __nv_bfloat16* Bs2[2] = { vsm + 128 * 40, vsm + VOC_STAGE + 128 * 40 };

    const int tid = threadIdx.x, lane = tid & 31, wid = tid >> 5;
    const int wm = (wid & 1) * 64;          // 2 M warps
    const int wn = (wid >> 1) * 32;         // 8 N warps
    const int m0 = blockIdx.x * 128, n0 = blockIdx.y * 256;
    const __nv_bfloat16* A = g_Sbf + (size_t)MEMN * SLOT;

    float acc[4][4][4] = {};

    voc_prefetch(A, m0, n0, 0, As2[0], Bs2[0], tid);
    for (int it = 0; it < 32; it++) {
        CPA_WAIT0();
        __syncthreads();
        if (it < 31)
            voc_prefetch(A, m0, n0, (it + 1) * 32, As2[(it + 1) & 1], Bs2[(it + 1) & 1], tid);
        __nv_bfloat16* As = As2[it & 1];
        __nv_bfloat16* Bs = Bs2[it & 1];
#pragma unroll
        for (int kk = 0; kk < 32; kk += 16) {
            unsigned af[4][4], bfm[4][2];
#pragma unroll
            for (int mi = 0; mi < 4; mi++)
                ldmx4(af[mi], su32(&As[(wm + mi * 16 + (lane & 15)) * 40 + kk + (lane >> 4) * 8]));
#pragma unroll
            for (int ni = 0; ni < 4; ni++)
                ldmx2(bfm[ni], su32(&Bs[(wn + ni * 8 + (lane & 7)) * 40 + kk + ((lane >> 3) & 1) * 8]));
#pragma unroll
            for (int mi = 0; mi < 4; mi++)
#pragma unroll
                for (int ni = 0; ni < 4; ni++)
                    mma16816(acc[mi][ni], af[mi], bfm[ni]);
        }
    }
#pragma unroll
    for (int mi = 0; mi < 4; mi++)
#pragma unroll
        for (int ni = 0; ni < 4; ni++) {
            int row = m0 + wm + mi * 16 + (lane >> 2);
            int col = n0 + wn + ni * 8 + (lane & 3) * 2;
            float b0 = b_out[col], b1 = b_out[col + 1];
            g_logits[(size_t)row * VOC + col]           = acc[mi][ni][0] + b0;
            g_logits[(size_t)row * VOC + col + 1]       = acc[mi][ni][1] + b1;
            g_logits[(size_t)(row + 8) * VOC + col]     = acc[mi][ni][2] + b0;
            g_logits[(size_t)(row + 8) * VOC + col + 1] = acc[mi][ni][3] + b1;
        }
}

// ---------------- persistent recurrence kernel (unchanged, known-good) ----------------
#define SM_RECUR ((8*1028 + 24*1028 + 2*32*132) * 4 + 8*32*24*4 + 128)

__global__ __launch_bounds__(256, 1) void k_recur()
{
    extern __shared__ __align__(16) char sm_raw[];
    uint32_t* wWp2 = (uint32_t*)sm_raw;
    uint32_t* wWhh = wWp2 + 8 * 1028;
    uint32_t* As2  = wWhh + 24 * 1028;
    float*    red  = (float*)(As2 + 2 * 32 * 132);
    float*    dots = red + 8 * 32 * 24;

    const int tid = threadIdx.x, blk = blockIdx.x;
    const int lane = tid & 31, wid = tid >> 5;
    const int r4 = lane >> 2, c4 = lane & 3;
    const int n0p = blk * 8, n0g = blk * 24, h0 = blk * 8;

    for (int i = tid; i < 8 * 1024; i += 256) {
        int r = i >> 10, k = i & 1023;
        wWp2[r * 1028 + k] = f2tf(g_Wp2f[(size_t)(n0p + r) * 1024 + k]);
    }
    for (int i = tid; i < 24 * 1024; i += 256) {
        int r = i >> 10, k = i & 1023;
        wWhh[r * 1028 + k] = f2tf(g_Whh3f[(size_t)(n0g + r) * 1024 + k]);
    }
    __syncthreads();

    unsigned target = 0;

    for (int t = 0; t < TN; t++) {
        {
            const float* Ap = g_S + (size_t)(t + 31) * SLOT;
            float accP[2][4] = {};
            float4 regs[4];
#pragma unroll
            for (int v = 0; v < 4; v++) {
                int idx = tid + v * 256;
                regs[v] = __ldcg((const float4*)&Ap[(size_t)(idx >> 5) * 1024 + (idx & 31) * 4]);
            }
            for (int c = 0; c < 8; c++) {
                uint32_t* Ab = As2 + (c & 1) * (32 * 132);
#pragma unroll
                for (int v = 0; v < 4; v++) {
                    int idx = tid + v * 256, row = idx >> 5, seg = idx & 31;
                    uint4 u;
                    u.x = f2tf(regs[v].x); u.y = f2tf(regs[v].y);
                    u.z = f2tf(regs[v].z); u.w = f2tf(regs[v].w);
                    *(uint4*)&Ab[row * 132 + seg * 4] = u;
                }
                __syncthreads();
                if (c < 7) {
#pragma unroll
                    for (int v = 0; v < 4; v++) {
                        int idx = tid + v * 256;
                        regs[v] = __ldcg((const float4*)&Ap[(size_t)(idx >> 5) * 1024 + (c + 1) * 128 + (idx & 31) * 4]);
                    }
                }
                int kb = wid * 16;
#pragma unroll
                for (int ks = 0; ks < 16; ks += 8) {
                    int kl = kb + ks, kg = c * 128 + kl;
                    uint32_t af[2][4], bf2[2];
#pragma unroll
                    for (int mi = 0; mi < 2; mi++) {
                        af[mi][0] = Ab[(mi * 16 + r4) * 132 + kl + c4];
                        af[mi][1] = Ab[(mi * 16 + r4 + 8) * 132 + kl + c4];
                        af[mi][2] = Ab[(mi * 16 + r4) * 132 + kl + c4 + 4];
                        af[mi][3] = Ab[(mi * 16 + r4 + 8) * 132 + kl + c4 + 4];
                    }
                    bf2[0] = wWp2[r4 * 1028 + kg + c4];
                    bf2[1] = wWp2[r4 * 1028 + kg + c4 + 4];
                    mma1688tf(accP[0], af[0], bf2);
                    mma1688tf(accP[1], af[1], bf2);
                }
            }
            {
                float* pr = red + wid * 256;
                int cb = (lane & 3) * 2;
#pragma unroll
                for (int mi = 0; mi < 2; mi++) {
                    int rr = mi * 16 + r4;
                    pr[rr * 8 + cb]           = accP[mi][0];
                    pr[rr * 8 + cb + 1]       = accP[mi][1];
                    pr[(rr + 8) * 8 + cb]     = accP[mi][2];
                    pr[(rr + 8) * 8 + cb + 1] = accP[mi][3];
                }
            }
            __syncthreads();
            {
                int row = tid >> 3, col = tid & 7;
                float s = 0.f;
#pragma unroll
                for (int w = 0; w < 8; w++) s += red[w * 256 + row * 8 + col];
                s += g_projA[(size_t)t * SLOT + row * 1024 + n0p + col];
                g_proj[row * 1024 + n0p + col] = s;
            }
        }
        gsync(target);

        if (blk < BAT) {
            const int b = blk;
            float* projS = (float*)As2;
#pragma unroll
            for (int p = 0; p < 4; p++)
                projS[tid + p * 256] = __ldcg(&g_proj[b * HID + tid + p * 256]);
            __syncthreads();
#pragma unroll
            for (int s = 0; s < 4; s++) {
                int m = wid * 4 + s;
                const float* mrow = g_S + (size_t)(t + 31 - m) * SLOT + b * HID;
                float sum = 0.f;
#pragma unroll
                for (int j = 0; j < 32; j++)
                    sum += __ldcg(&mrow[lane + 32 * j]) * projS[lane + 32 * j];
#pragma unroll
                for (int o = 16; o; o >>= 1) sum += __shfl_xor_sync(~0u, sum, o);
                if (lane == 0) dots[m] = sum * 0.03125f;
            }
            __syncthreads();
            if (wid == 0) {
                float d = dots[lane], mx = d;
#pragma unroll
                for (int o = 16; o; o >>= 1) mx = fmaxf(mx, __shfl_xor_sync(~0u, mx, o));
                float e = expf(d - mx), ss = e;
#pragma unroll
                for (int o = 16; o; o >>= 1) ss += __shfl_xor_sync(~0u, ss, o);
                dots[lane] = e / ss;
            }
            __syncthreads();
#pragma unroll
            for (int p = 0; p < 4; p++) {
                int h = tid + p * 256;
                float acc = 0.f;
#pragma unroll
                for (int m = 0; m < 32; m++)
                    acc += dots[m] * __ldcg(&g_S[(size_t)(t + 31 - m) * SLOT + b * HID + h]);
                g_sel[b * HID + h] = acc;
            }
        }
        gsync(target);

        {
            float accG[2][3][4] = {};
            float4 regs[4];
#pragma unroll
            for (int v = 0; v < 4; v++) {
                int idx = tid + v * 256;
                regs[v] = __ldcg((const float4*)&g_sel[(size_t)(idx >> 5) * 1024 + (idx & 31) * 4]);
            }
            for (int c = 0; c < 8; c++) {
                uint32_t* Ab = As2 + (c & 1) * (32 * 132);
#pragma unroll
                for (int v = 0; v < 4; v++) {
                    int idx = tid + v * 256, row = idx >> 5, seg = idx & 31;
                    uint4 u;
                    u.x = f2tf(regs[v].x); u.y = f2tf(regs[v].y);
                    u.z = f2tf(regs[v].z); u.w = f2tf(regs[v].w);
                    *(uint4*)&Ab[row * 132 + seg * 4] = u;
                }
                __syncthreads();
                if (c < 7) {
#pragma unroll
                    for (int v = 0; v < 4; v++) {
                        int idx = tid + v * 256;
                        regs[v] = __ldcg((const float4*)&g_sel[(size_t)(idx >> 5) * 1024 + (c + 1) * 128 + (idx & 31) * 4]);
                    }
                }
                int kb = wid * 16;
#pragma unroll
                for (int ks = 0; ks < 16; ks += 8) {
                    int kl = kb + ks, kg = c * 128 + kl;
                    uint32_t af[2][4];
#pragma unroll
                    for (int mi = 0; mi < 2; mi++) {
                        af[mi][0] = Ab[(mi * 16 + r4) * 132 + kl + c4];
                        af[mi][1] = Ab[(mi * 16 + r4 + 8) * 132 + kl + c4];
                        af[mi][2] = Ab[(mi * 16 + r4) * 132 + kl + c4 + 4];
                        af[mi][3] = Ab[(mi * 16 + r4 + 8) * 132 + kl + c4 + 4];
                    }
#pragma unroll
                    for (int ni = 0; ni < 3; ni++) {
                        uint32_t bf2[2] = { wWhh[(ni * 8 + r4) * 1028 + kg + c4],
                                            wWhh[(ni * 8 + r4) * 1028 + kg + c4 + 4] };
                        mma1688tf(accG[0][ni], af[0], bf2);
                        mma1688tf(accG[1][ni], af[1], bf2);
                    }
                }
            }
            {
                float* pr = red + wid * 768;
                int cb = (lane & 3) * 2;
#pragma unroll
                for (int mi = 0; mi < 2; mi++)
#pragma unroll
                    for (int ni = 0; ni < 3; ni++) {
                        int rr = mi * 16 + r4, cc = ni * 8 + cb;
                        pr[rr * 24 + cc]           = accG[mi][ni][0];
                        pr[rr * 24 + cc + 1]       = accG[mi][ni][1];
                        pr[(rr + 8) * 24 + cc]     = accG[mi][ni][2];
                        pr[(rr + 8) * 24 + cc + 1] = accG[mi][ni][3];
                    }
            }
            __syncthreads();
            {
                int b = tid >> 3, hh = tid & 7;
                float gg[3];
#pragma unroll
                for (int g = 0; g < 3; g++) {
                    float s = g_bhh3[n0g + 3 * hh + g];
#pragma unroll
                    for (int w = 0; w < 8; w++) s += red[w * 768 + b * 24 + 3 * hh + g];
                    gg[g] = s;
                }
                const float* gi = g_giAll + (size_t)(t * BAT + b) * G3 + n0g + 3 * hh;
                float r = 1.f / (1.f + expf(-(gi[0] + gg[0])));
                float z = 1.f / (1.f + expf(-(gi[1] + gg[1])));
                float n = tanhf(gi[2] + r * gg[2]);
                float sv = __ldcg(&g_sel[b * HID + h0 + hh]);
                float hv = (1.f - z) * n + z * sv;
                size_t o = (size_t)(MEMN + t) * SLOT + b * HID + h0 + hh;
                g_S[o] = hv;
                g_Sbf[o] = __float2bfloat16_rn(hv);
            }
        }
        gsync(target);
    }
}

// ---------------- fused log-softmax + transposed write (online logsumexp) ----------------
__global__ __launch_bounds__(256) void k_lseout(float* __restrict__ out)
{
    const int r = blockIdx.x;            // r = t*BAT + b
    const int t = r >> 5, b = r & 31;
    const float* row = g_logits + (size_t)r * VOC;
    __shared__ float sm_m[8], sm_s[8], lse_sh;
    int tid = threadIdx.x, lane = tid & 31, wid = tid >> 5;

    float m = -1e30f, ssum = 0.f;
    for (int i = tid; i < VOC; i += 256) {
        float x = row[i];
        if (x > m) { ssum = ssum * expf(m - x) + 1.f; m = x; }
        else       { ssum += expf(x - m); }
    }
#pragma unroll
    for (int o = 16; o; o >>= 1) {
        float m2 = __shfl_xor_sync(~0u, m, o);
        float s2 = __shfl_xor_sync(~0u, ssum, o);
        float mn = fmaxf(m, m2);
        ssum = ssum * expf(m - mn) + s2 * expf(m2 - mn);
        m = mn;
    }
    if (lane == 0) { sm_m[wid] = m; sm_s[wid] = ssum; }
    __syncthreads();
    if (tid == 0) {
        float M = sm_m[0];
        for (int w = 1; w < 8; w++) M = fmaxf(M, sm_m[w]);
        float S = 0.f;
        for (int w = 0; w < 8; w++) S += sm_s[w] * expf(sm_m[w] - M);
        lse_sh = M + logf(S);
    }
    __syncthreads();
    float l = lse_sh;
    const float4* src = (const float4*)row;
    float4* dst = (float4*)(out + ((size_t)b * TN + t) * VOC);
    for (int i = tid; i < VOC / 4; i += 256) {
        float4 v = src[i];
        v.x -= l; v.y -= l; v.z -= l; v.w -= l;
        dst[i] = v;
    }
}

// out2 (MEM,B,H): out2[m][b][h] = S[95-m][b][h]
__global__ void k_outmem(float* __restrict__ out2)
{
    int idx = blockIdx.x * 256 + threadIdx.x;
    int m = idx / (SLOT / 4);
    int rest = idx % (SLOT / 4);
    const float4* src = (const float4*)(g_S + (size_t)(MEMN + TN - 1 - m) * SLOT);
    float4* dst = (float4*)(out2 + (size_t)m * SLOT);
    dst[rest] = src[rest];
}

// ---------------- launch ----------------
extern "C" void kernel_launch(void* const* d_in, const int* in_sizes, int n_in,
                              void* d_out, int out_size)
{
    const int*   input  = (const int*)  d_in[0];
    const float* memory = (const float*)d_in[1];
    const float* emb    = (const float*)d_in[2];
    const float* W_proj = (const float*)d_in[3];
    const float* b_proj = (const float*)d_in[4];
    const float* W_ih   = (const float*)d_in[5];
    const float* W_hh   = (const float*)d_in[6];
    const float* b_ih   = (const float*)d_in[7];
    const float* b_hh   = (const float*)d_in[8];
    const float* W_out  = (const float*)d_in[9];
    const float* b_out  = (const float*)d_in[10];
    float* out = (float*)d_out;

    cudaFuncSetAttribute(k_recur, cudaFuncAttributeMaxDynamicSharedMemorySize, SM_RECUR);
    cudaFuncSetAttribute(k_voc, cudaFuncAttributeMaxDynamicSharedMemorySize, 2 * VOC_STAGE * 2);

    k_prepA<<<WOUTB + 24576 + 4096 + 12, 256>>>(W_out, W_ih, W_hh, W_proj, b_ih, b_hh); // 1
    k_prepB<<<8192 + 4096, 256>>>(input, emb, memory);                                  // 2
    k_gemm_all<<<dim3(16, 32), 256>>>(b_proj);                                          // 3
    k_recur<<<NBLK, 256, SM_RECUR>>>();                                                 // 4
    k_outmem<<<(MEMN * SLOT / 4) / 256, 256>>>(out + (size_t)BAT * TN * VOC);           // 5
    k_voc<<<dim3(16, 125), 512, 2 * VOC_STAGE * 2>>>(b_out);                            // 6 (ncu -s 5 target)
    k_lseout<<<RN, 256>>>(out);                                                         // 7
}

// round 15
// speedup vs baseline: 1.0555x; 1.0555x over previous
#include <cuda_runtime.h>
#include <cuda_bf16.h>
#include <math.h>
#include <stdint.h>

#define HID 1024
#define VOC 32000
#define MEMN 32
#define BAT 32
#define TN 64
#define RN (TN*BAT)      // 2048
#define G3 (3*HID)       // 3072
#define SLOT (BAT*HID)   // 32768
#define NBLK 128
#define WOUTB 128000     // (VOC*HID)/256 blocks for W_out conversion

// ---------------- device scratch (static, no allocs) ----------------
__device__ __align__(16) __nv_bfloat16 g_Wout[(size_t)VOC*HID];
__device__ __align__(16) __nv_bfloat16 g_Wih3[(size_t)G3*HID];   // bf16, rows permuted 3*h+g
__device__ __align__(16) float g_Whh3f[(size_t)G3*HID];          // f32, rows permuted 3*h+g
__device__ __align__(16) float g_bih3[G3];
__device__ __align__(16) float g_bhh3[G3];
__device__ __align__(16) __nv_bfloat16 g_Wp1[(size_t)HID*HID];   // bf16 x-half of W_proj
__device__ __align__(16) float g_Wp2f[(size_t)HID*HID];          // f32 mem-half of W_proj
__device__ __align__(16) __nv_bfloat16 g_xbf[(size_t)RN*HID];    // relu(emb), rows (t*B+b)
__device__ __align__(16) float         g_S  [(size_t)(MEMN+TN)*SLOT];  // state ring f32
__device__ __align__(16) __nv_bfloat16 g_Sbf[(size_t)(MEMN+TN)*SLOT];  // state ring bf16
__device__ __align__(16) float g_giAll[(size_t)RN*G3];           // x@W_ih^T+b_ih (perm cols)
__device__ __align__(16) float g_projA[(size_t)RN*HID];          // x@Wp1^T+b_proj
__device__ __align__(16) float g_proj[(size_t)BAT*HID];
__device__ __align__(16) float g_sel[(size_t)BAT*HID];
__device__ __align__(16) float g_logits[(size_t)RN*VOC];
__device__ unsigned g_barCnt;

// ---------------- helpers ----------------
__device__ __forceinline__ unsigned su32(const void* p) {
    return (unsigned)__cvta_generic_to_shared(p);
}
__device__ __forceinline__ void cpa16(void* smem_dst, const void* gsrc) {
    asm volatile("cp.async.cg.shared.global [%0], [%1], 16;"
                 :: "r"(su32(smem_dst)), "l"(gsrc));
}
#define CPA_COMMIT() asm volatile("cp.async.commit_group;")
#define CPA_WAIT0()  asm volatile("cp.async.wait_group 0;" ::: "memory")

__device__ __forceinline__ void ldmx4(unsigned* r, unsigned a) {
    asm volatile("ldmatrix.sync.aligned.m8n8.x4.shared.b16 {%0,%1,%2,%3},[%4];"
                 : "=r"(r[0]), "=r"(r[1]), "=r"(r[2]), "=r"(r[3]) : "r"(a));
}
__device__ __forceinline__ void ldmx2(unsigned* r, unsigned a) {
    asm volatile("ldmatrix.sync.aligned.m8n8.x2.shared.b16 {%0,%1},[%2];"
                 : "=r"(r[0]), "=r"(r[1]) : "r"(a));
}
__device__ __forceinline__ void mma16816(float* c, const unsigned* a, const unsigned* b) {
    asm volatile(
        "mma.sync.aligned.m16n8k16.row.col.f32.bf16.bf16.f32 "
        "{%0,%1,%2,%3},{%4,%5,%6,%7},{%8,%9},{%0,%1,%2,%3};"
        : "+f"(c[0]), "+f"(c[1]), "+f"(c[2]), "+f"(c[3])
        : "r"(a[0]), "r"(a[1]), "r"(a[2]), "r"(a[3]), "r"(b[0]), "r"(b[1]));
}
__device__ __forceinline__ uint32_t f2tf(float f) {
    uint32_t r;
    asm("cvt.rna.tf32.f32 %0, %1;" : "=r"(r) : "f"(f));
    return r;
}
__device__ __forceinline__ void mma1688tf(float* c, const uint32_t* a, const uint32_t* b) {
    asm volatile(
        "mma.sync.aligned.m16n8k8.row.col.f32.tf32.tf32.f32 "
        "{%0,%1,%2,%3},{%4,%5,%6,%7},{%8,%9},{%0,%1,%2,%3};"
        : "+f"(c[0]), "+f"(c[1]), "+f"(c[2]), "+f"(c[3])
        : "r"(a[0]), "r"(a[1]), "r"(a[2]), "r"(a[3]), "r"(b[0]), "r"(b[1]));
}

// ---------------- grid barrier (monotonic counter) ----------------
__device__ __forceinline__ unsigned ldacq(const unsigned* p) {
    unsigned v;
    asm volatile("ld.acquire.gpu.global.u32 %0, [%1];" : "=r"(v) : "l"(p));
    return v;
}
__device__ __forceinline__ void gsync(unsigned &target) {
    __syncthreads();
    if (threadIdx.x == 0) {
        __threadfence();
        atomicAdd(&g_barCnt, 1u);
        target += NBLK;
        while (ldacq(&g_barCnt) < target) { }
    }
    __syncthreads();
}

// ---------------- prep kernels ----------------
__global__ void k_prepA(const float* __restrict__ W_out, const float* __restrict__ W_ih,
                        const float* __restrict__ W_hh, const float* __restrict__ W_proj,
                        const float* __restrict__ b_ih, const float* __restrict__ b_hh) {
    int blk = blockIdx.x, tid = threadIdx.x;
    if (blk < WOUTB) {
        size_t i = (size_t)blk * 256 + tid;
        g_Wout[i] = __float2bfloat16_rn(W_out[i]);
    } else if (blk < WOUTB + 12288) {
        int i = (blk - WOUTB) * 256 + tid;
        int srow = i >> 10, k = i & 1023;
        int g = srow >> 10, h = srow & 1023;
        g_Wih3[((size_t)(3*h + g) << 10) | k] = __float2bfloat16_rn(W_ih[i]);
    } else if (blk < WOUTB + 24576) {
        int i = (blk - WOUTB - 12288) * 256 + tid;
        int srow = i >> 10, k = i & 1023;
        int g = srow >> 10, h = srow & 1023;
        g_Whh3f[((size_t)(3*h + g) << 10) | k] = W_hh[i];
    } else if (blk < WOUTB + 24576 + 4096) {
        int i = (blk - WOUTB - 24576) * 256 + tid;
        int j = i >> 10, k = i & 1023;
        g_Wp1[i]  = __float2bfloat16_rn(W_proj[(size_t)j * 2048 + k]);
        g_Wp2f[i] = W_proj[(size_t)j * 2048 + 1024 + k];
    } else {
        int i = (blk - WOUTB - 24576 - 4096) * 256 + tid;
        if (i < G3) {
            int g = i >> 10, h = i & 1023;
            g_bih3[3*h + g] = b_ih[i];
            g_bhh3[3*h + g] = b_hh[i];
        }
    }
}
__global__ void k_prepB(const int* __restrict__ input, const float* __restrict__ emb,
                        const float* __restrict__ memory) {
    int blk = blockIdx.x, tid = threadIdx.x;
    if (blk == 0 && tid == 0) g_barCnt = 0;
    if (blk < 8192) {
        int idx = blk * 256 + tid;
        int r = idx >> 10, h = idx & 1023;
        int t = r >> 5, b = r & 31;
        int tok = input[b * TN + t];
        float v = emb[(size_t)tok * HID + h];
        g_xbf[idx] = __float2bfloat16_rn(v > 0.f ? v : 0.f);
    } else {
        int idx = (blk - 8192) * 256 + tid;
        int k = idx >> 15, rest = idx & 32767;
        float v = memory[(size_t)(31 - k) * SLOT + rest];
        g_S[idx] = v;
        g_Sbf[idx] = __float2bfloat16_rn(v);
    }
}

// ---------------- bf16 128x128 GEMM body, cp.async 2-stage pipelined ----------------
__device__ __forceinline__ void gemm_prefetch(
    const __nv_bfloat16* A, const __nv_bfloat16* Wt, int m0, int n0, int k0,
    __nv_bfloat16 (*As)[40], __nv_bfloat16 (*Bs)[40], int tid)
{
#pragma unroll
    for (int v = 0; v < 2; v++) {
        int task = tid + v * 256;
        int row = task >> 2, seg = task & 3;
        cpa16(&As[row][seg * 8], &A [(size_t)(m0 + row) * 1024 + k0 + seg * 8]);
        cpa16(&Bs[row][seg * 8], &Wt[(size_t)(n0 + row) * 1024 + k0 + seg * 8]);
    }
    CPA_COMMIT();
}

__device__ __forceinline__ void gemm128_body(
    const __nv_bfloat16* __restrict__ A, const __nv_bfloat16* __restrict__ Wt,
    const float* __restrict__ bias, float* __restrict__ C, int N, int m0, int n0,
    __nv_bfloat16 (*As2)[128][40], __nv_bfloat16 (*Bs2)[128][40])
{
    const int tid = threadIdx.x, lane = tid & 31, wid = tid >> 5;
    const int wm = (wid & 1) * 64;
    const int wn = (wid >> 1) * 32;
    float acc[4][4][4] = {};

    gemm_prefetch(A, Wt, m0, n0, 0, As2[0], Bs2[0], tid);
    for (int it = 0; it < 32; it++) {
        CPA_WAIT0();
        __syncthreads();
        if (it < 31)
            gemm_prefetch(A, Wt, m0, n0, (it + 1) * 32, As2[(it + 1) & 1], Bs2[(it + 1) & 1], tid);
        __nv_bfloat16 (*As)[40] = As2[it & 1];
        __nv_bfloat16 (*Bs)[40] = Bs2[it & 1];
#pragma unroll
        for (int kk = 0; kk < 32; kk += 16) {
            unsigned af[4][4], bfm[4][2];
#pragma unroll
            for (int mi = 0; mi < 4; mi++)
                ldmx4(af[mi], su32(&As[wm + mi * 16 + (lane & 15)][kk + (lane >> 4) * 8]));
#pragma unroll
            for (int ni = 0; ni < 4; ni++)
                ldmx2(bfm[ni], su32(&Bs[wn + ni * 8 + (lane & 7)][kk + ((lane >> 3) & 1) * 8]));
#pragma unroll
            for (int mi = 0; mi < 4; mi++)
#pragma unroll
                for (int ni = 0; ni < 4; ni++)
                    mma16816(acc[mi][ni], af[mi], bfm[ni]);
        }
    }
#pragma unroll
    for (int mi = 0; mi < 4; mi++)
#pragma unroll
        for (int ni = 0; ni < 4; ni++) {
            int row = m0 + wm + mi * 16 + (lane >> 2);
            int col = n0 + wn + ni * 8 + (lane & 3) * 2;
            float b0 = bias[col], b1 = bias[col + 1];
            C[(size_t)row * N + col]           = acc[mi][ni][0] + b0;
            C[(size_t)row * N + col + 1]       = acc[mi][ni][1] + b1;
            C[(size_t)(row + 8) * N + col]     = acc[mi][ni][2] + b0;
            C[(size_t)(row + 8) * N + col + 1] = acc[mi][ni][3] + b1;
        }
}

// gi (y<24) + projA (y>=24) in one launch
__global__ __launch_bounds__(256) void k_gemm_all(const float* __restrict__ b_proj)
{
    __shared__ __align__(16) __nv_bfloat16 As2[2][128][40];
    __shared__ __align__(16) __nv_bfloat16 Bs2[2][128][40];
    int m0 = blockIdx.x * 128;
    if (blockIdx.y < 24)
        gemm128_body(g_xbf, g_Wih3, g_bih3, g_giAll, G3, m0, blockIdx.y * 128, As2, Bs2);
    else
        gemm128_body(g_xbf, g_Wp1, b_proj, g_projA, HID, m0, (blockIdx.y - 24) * 128, As2, Bs2);
}
// vocab projection — proven 128x128 multi-block-per-SM config
__global__ __launch_bounds__(256) void k_gemm_voc(const float* __restrict__ b_out)
{
    __shared__ __align__(16) __nv_bfloat16 As2[2][128][40];
    __shared__ __align__(16) __nv_bfloat16 Bs2[2][128][40];
    gemm128_body(g_Sbf + (size_t)MEMN * SLOT, g_Wout, b_out, g_logits, VOC,
                 blockIdx.x * 128, blockIdx.y * 128, As2, Bs2);
}

// ---------------- persistent recurrence kernel (unchanged, known-good) ----------------
#define SM_RECUR ((8*1028 + 24*1028 + 2*32*132) * 4 + 8*32*24*4 + 128)

__global__ __launch_bounds__(256, 1) void k_recur()
{
    extern __shared__ __align__(16) char sm_raw[];
    uint32_t* wWp2 = (uint32_t*)sm_raw;
    uint32_t* wWhh = wWp2 + 8 * 1028;
    uint32_t* As2  = wWhh + 24 * 1028;
    float*    red  = (float*)(As2 + 2 * 32 * 132);
    float*    dots = red + 8 * 32 * 24;

    const int tid = threadIdx.x, blk = blockIdx.x;
    const int lane = tid & 31, wid = tid >> 5;
    const int r4 = lane >> 2, c4 = lane & 3;
    const int n0p = blk * 8, n0g = blk * 24, h0 = blk * 8;

    for (int i = tid; i < 8 * 1024; i += 256) {
        int r = i >> 10, k = i & 1023;
        wWp2[r * 1028 + k] = f2tf(g_Wp2f[(size_t)(n0p + r) * 1024 + k]);
    }
    for (int i = tid; i < 24 * 1024; i += 256) {
        int r = i >> 10, k = i & 1023;
        wWhh[r * 1028 + k] = f2tf(g_Whh3f[(size_t)(n0g + r) * 1024 + k]);
    }
    __syncthreads();

    unsigned target = 0;

    for (int t = 0; t < TN; t++) {
        {
            const float* Ap = g_S + (size_t)(t + 31) * SLOT;
            float accP[2][4] = {};
            float4 regs[4];
#pragma unroll
            for (int v = 0; v < 4; v++) {
                int idx = tid + v * 256;
                regs[v] = __ldcg((const float4*)&Ap[(size_t)(idx >> 5) * 1024 + (idx & 31) * 4]);
            }
            for (int c = 0; c < 8; c++) {
                uint32_t* Ab = As2 + (c & 1) * (32 * 132);
#pragma unroll
                for (int v = 0; v < 4; v++) {
                    int idx = tid + v * 256, row = idx >> 5, seg = idx & 31;
                    uint4 u;
                    u.x = f2tf(regs[v].x); u.y = f2tf(regs[v].y);
                    u.z = f2tf(regs[v].z); u.w = f2tf(regs[v].w);
                    *(uint4*)&Ab[row * 132 + seg * 4] = u;
                }
                __syncthreads();
                if (c < 7) {
#pragma unroll
                    for (int v = 0; v < 4; v++) {
                        int idx = tid + v * 256;
                        regs[v] = __ldcg((const float4*)&Ap[(size_t)(idx >> 5) * 1024 + (c + 1) * 128 + (idx & 31) * 4]);
                    }
                }
                int kb = wid * 16;
#pragma unroll
                for (int ks = 0; ks < 16; ks += 8) {
                    int kl = kb + ks, kg = c * 128 + kl;
                    uint32_t af[2][4], bf2[2];
#pragma unroll
                    for (int mi = 0; mi < 2; mi++) {
                        af[mi][0] = Ab[(mi * 16 + r4) * 132 + kl + c4];
                        af[mi][1] = Ab[(mi * 16 + r4 + 8) * 132 + kl + c4];
                        af[mi][2] = Ab[(mi * 16 + r4) * 132 + kl + c4 + 4];
                        af[mi][3] = Ab[(mi * 16 + r4 + 8) * 132 + kl + c4 + 4];
                    }
                    bf2[0] = wWp2[r4 * 1028 + kg + c4];
                    bf2[1] = wWp2[r4 * 1028 + kg + c4 + 4];
                    mma1688tf(accP[0], af[0], bf2);
                    mma1688tf(accP[1], af[1], bf2);
                }
            }
            {
                float* pr = red + wid * 256;
                int cb = (lane & 3) * 2;
#pragma unroll
                for (int mi = 0; mi < 2; mi++) {
                    int rr = mi * 16 + r4;
                    pr[rr * 8 + cb]           = accP[mi][0];
                    pr[rr * 8 + cb + 1]       = accP[mi][1];
                    pr[(rr + 8) * 8 + cb]     = accP[mi][2];
                    pr[(rr + 8) * 8 + cb + 1] = accP[mi][3];
                }
            }
            __syncthreads();
            {
                int row = tid >> 3, col = tid & 7;
                float s = 0.f;
#pragma unroll
                for (int w = 0; w < 8; w++) s += red[w * 256 + row * 8 + col];
                s += g_projA[(size_t)t * SLOT + row * 1024 + n0p + col];
                g_proj[row * 1024 + n0p + col] = s;
            }
        }
        gsync(target);

        if (blk < BAT) {
            const int b = blk;
            float* projS = (float*)As2;
#pragma unroll
            for (int p = 0; p < 4; p++)
                projS[tid + p * 256] = __ldcg(&g_proj[b * HID + tid + p * 256]);
            __syncthreads();
#pragma unroll
            for (int s = 0; s < 4; s++) {
                int m = wid * 4 + s;
                const float* mrow = g_S + (size_t)(t + 31 - m) * SLOT + b * HID;
                float sum = 0.f;
#pragma unroll
                for (int j = 0; j < 32; j++)
                    sum += __ldcg(&mrow[lane + 32 * j]) * projS[lane + 32 * j];
#pragma unroll
                for (int o = 16; o; o >>= 1) sum += __shfl_xor_sync(~0u, sum, o);
                if (lane == 0) dots[m] = sum * 0.03125f;
            }
            __syncthreads();
            if (wid == 0) {
                float d = dots[lane], mx = d;
#pragma unroll
                for (int o = 16; o; o >>= 1) mx = fmaxf(mx, __shfl_xor_sync(~0u, mx, o));
                float e = expf(d - mx), ss = e;
#pragma unroll
                for (int o = 16; o; o >>= 1) ss += __shfl_xor_sync(~0u, ss, o);
                dots[lane] = e / ss;
            }
            __syncthreads();
#pragma unroll
            for (int p = 0; p < 4; p++) {
                int h = tid + p * 256;
                float acc = 0.f;
#pragma unroll
                for (int m = 0; m < 32; m++)
                    acc += dots[m] * __ldcg(&g_S[(size_t)(t + 31 - m) * SLOT + b * HID + h]);
                g_sel[b * HID + h] = acc;
            }
        }
        gsync(target);

        {
            float accG[2][3][4] = {};
            float4 regs[4];
#pragma unroll
            for (int v = 0; v < 4; v++) {
                int idx = tid + v * 256;
                regs[v] = __ldcg((const float4*)&g_sel[(size_t)(idx >> 5) * 1024 + (idx & 31) * 4]);
            }
            for (int c = 0; c < 8; c++) {
                uint32_t* Ab = As2 + (c & 1) * (32 * 132);
#pragma unroll
                for (int v = 0; v < 4; v++) {
                    int idx = tid + v * 256, row = idx >> 5, seg = idx & 31;
                    uint4 u;
                    u.x = f2tf(regs[v].x); u.y = f2tf(regs[v].y);
                    u.z = f2tf(regs[v].z); u.w = f2tf(regs[v].w);
                    *(uint4*)&Ab[row * 132 + seg * 4] = u;
                }
                __syncthreads();
                if (c < 7) {
#pragma unroll
                    for (int v = 0; v < 4; v++) {
                        int idx = tid + v * 256;
                        regs[v] = __ldcg((const float4*)&g_sel[(size_t)(idx >> 5) * 1024 + (c + 1) * 128 + (idx & 31) * 4]);
                    }
                }
                int kb = wid * 16;
#pragma unroll
                for (int ks = 0; ks < 16; ks += 8) {
                    int kl = kb + ks, kg = c * 128 + kl;
                    uint32_t af[2][4];
#pragma unroll
                    for (int mi = 0; mi < 2; mi++) {
                        af[mi][0] = Ab[(mi * 16 + r4) * 132 + kl + c4];
                        af[mi][1] = Ab[(mi * 16 + r4 + 8) * 132 + kl + c4];
                        af[mi][2] = Ab[(mi * 16 + r4) * 132 + kl + c4 + 4];
                        af[mi][3] = Ab[(mi * 16 + r4 + 8) * 132 + kl + c4 + 4];
                    }
#pragma unroll
                    for (int ni = 0; ni < 3; ni++) {
                        uint32_t bf2[2] = { wWhh[(ni * 8 + r4) * 1028 + kg + c4],
                                            wWhh[(ni * 8 + r4) * 1028 + kg + c4 + 4] };
                        mma1688tf(accG[0][ni], af[0], bf2);
                        mma1688tf(accG[1][ni], af[1], bf2);
                    }
                }
            }
            {
                float* pr = red + wid * 768;
                int cb = (lane & 3) * 2;
#pragma unroll
                for (int mi = 0; mi < 2; mi++)
#pragma unroll
                    for (int ni = 0; ni < 3; ni++) {
                        int rr = mi * 16 + r4, cc = ni * 8 + cb;
                        pr[rr * 24 + cc]           = accG[mi][ni][0];
                        pr[rr * 24 + cc + 1]       = accG[mi][ni][1];
                        pr[(rr + 8) * 24 + cc]     = accG[mi][ni][2];
                        pr[(rr + 8) * 24 + cc + 1] = accG[mi][ni][3];
                    }
            }
            __syncthreads();
            {
                int b = tid >> 3, hh = tid & 7;
                float gg[3];
#pragma unroll
                for (int g = 0; g < 3; g++) {
                    float s = g_bhh3[n0g + 3 * hh + g];
#pragma unroll
                    for (int w = 0; w < 8; w++) s += red[w * 768 + b * 24 + 3 * hh + g];
                    gg[g] = s;
                }
                const float* gi = g_giAll + (size_t)(t * BAT + b) * G3 + n0g + 3 * hh;
                float r = 1.f / (1.f + expf(-(gi[0] + gg[0])));
                float z = 1.f / (1.f + expf(-(gi[1] + gg[1])));
                float n = tanhf(gi[2] + r * gg[2]);
                float sv = __ldcg(&g_sel[b * HID + h0 + hh]);
                float hv = (1.f - z) * n + z * sv;
                size_t o = (size_t)(MEMN + t) * SLOT + b * HID + h0 + hh;
                g_S[o] = hv;
                g_Sbf[o] = __float2bfloat16_rn(hv);
            }
        }
        gsync(target);
    }
}

// ---------------- fused log-softmax + transposed write (online logsumexp) ----------------
__global__ __launch_bounds__(256) void k_lseout(float* __restrict__ out)
{
    const int r = blockIdx.x;            // r = t*BAT + b
    const int t = r >> 5, b = r & 31;
    const float* row = g_logits + (size_t)r * VOC;
    __shared__ float sm_m[8], sm_s[8], lse_sh;
    int tid = threadIdx.x, lane = tid & 31, wid = tid >> 5;

    float m = -1e30f, ssum = 0.f;
    for (int i = tid; i < VOC; i += 256) {
        float x = row[i];
        if (x > m) { ssum = ssum * expf(m - x) + 1.f; m = x; }
        else       { ssum += expf(x - m); }
    }
#pragma unroll
    for (int o = 16; o; o >>= 1) {
        float m2 = __shfl_xor_sync(~0u, m, o);
        float s2 = __shfl_xor_sync(~0u, ssum, o);
        float mn = fmaxf(m, m2);
        ssum = ssum * expf(m - mn) + s2 * expf(m2 - mn);
        m = mn;
    }
    if (lane == 0) { sm_m[wid] = m; sm_s[wid] = ssum; }
    __syncthreads();
    if (tid == 0) {
        float M = sm_m[0];
        for (int w = 1; w < 8; w++) M = fmaxf(M, sm_m[w]);
        float S = 0.f;
        for (int w = 0; w < 8; w++) S += sm_s[w] * expf(sm_m[w] - M);
        lse_sh = M + logf(S);
    }
    __syncthreads();
    float l = lse_sh;
    const float4* src = (const float4*)row;
    float4* dst = (float4*)(out + ((size_t)b * TN + t) * VOC);
    for (int i = tid; i < VOC / 4; i += 256) {
        float4 v = src[i];
        v.x -= l; v.y -= l; v.z -= l; v.w -= l;
        dst[i] = v;
    }
}

// out2 (MEM,B,H): out2[m][b][h] = S[95-m][b][h]
__global__ void k_outmem(float* __restrict__ out2)
{
    int idx = blockIdx.x * 256 + threadIdx.x;
    int m = idx / (SLOT / 4);
    int rest = idx % (SLOT / 4);
    const float4* src = (const float4*)(g_S + (size_t)(MEMN + TN - 1 - m) * SLOT);
    float4* dst = (float4*)(out2 + (size_t)m * SLOT);
    dst[rest] = src[rest];
}

// ---------------- launch ----------------
extern "C" void kernel_launch(void* const* d_in, const int* in_sizes, int n_in,
                              void* d_out, int out_size)
{
    const int*   input  = (const int*)  d_in[0];
    const float* memory = (const float*)d_in[1];
    const float* emb    = (const float*)d_in[2];
    const float* W_proj = (const float*)d_in[3];
    const float* b_proj = (const float*)d_in[4];
    const float* W_ih   = (const float*)d_in[5];
    const float* W_hh   = (const float*)d_in[6];
    const float* b_ih   = (const float*)d_in[7];
    const float* b_hh   = (const float*)d_in[8];
    const float* W_out  = (const float*)d_in[9];
    const float* b_out  = (const float*)d_in[10];
    float* out = (float*)d_out;

    cudaFuncSetAttribute(k_recur, cudaFuncAttributeMaxDynamicSharedMemorySize, SM_RECUR);

    k_prepA<<<WOUTB + 24576 + 4096 + 12, 256>>>(W_out, W_ih, W_hh, W_proj, b_ih, b_hh); // 1
    k_prepB<<<8192 + 4096, 256>>>(input, emb, memory);                                  // 2
    k_gemm_all<<<dim3(16, 32), 256>>>(b_proj);                                          // 3
    k_recur<<<NBLK, 256, SM_RECUR>>>();                                                 // 4
    k_outmem<<<(MEMN * SLOT / 4) / 256, 256>>>(out + (size_t)BAT * TN * VOC);           // 5
    k_gemm_voc<<<dim3(16, 250), 256>>>(b_out);                                          // 6 (ncu -s 5 target)
    k_lseout<<<RN, 256>>>(out);                                                         // 7
}

// round 16
// speedup vs baseline: 1.1159x; 1.0572x over previous
#include <cuda_runtime.h>
#include <cuda_bf16.h>
#include <math.h>
#include <stdint.h>

#define HID 1024
#define VOC 32000
#define MEMN 32
#define BAT 32
#define TN 64
#define RN (TN*BAT)      // 2048
#define G3 (3*HID)       // 3072
#define SLOT (BAT*HID)   // 32768
#define NBLK 128
#define WOUTB 128000     // (VOC*HID)/256 blocks for W_out conversion

// ---------------- device scratch (static, no allocs) ----------------
__device__ __align__(16) __nv_bfloat16 g_Wout[(size_t)VOC*HID];
__device__ __align__(16) __nv_bfloat16 g_Wih3[(size_t)G3*HID];   // bf16, rows permuted 3*h+g
__device__ __align__(16) float g_Whh3f[(size_t)G3*HID];          // f32, rows permuted 3*h+g
__device__ __align__(16) float g_bih3[G3];
__device__ __align__(16) float g_bhh3[G3];
__device__ __align__(16) __nv_bfloat16 g_Wp1[(size_t)HID*HID];   // bf16 x-half of W_proj
__device__ __align__(16) float g_Wp2f[(size_t)HID*HID];          // f32 mem-half of W_proj
__device__ __align__(16) __nv_bfloat16 g_xbf[(size_t)RN*HID];    // relu(emb), rows (t*B+b)
__device__ __align__(16) float         g_S  [(size_t)(MEMN+TN)*SLOT];  // state ring f32
__device__ __align__(16) __nv_bfloat16 g_Sbf[(size_t)(MEMN+TN)*SLOT];  // state ring bf16
__device__ __align__(16) float g_giAll[(size_t)RN*G3];           // x@W_ih^T+b_ih (perm cols)
__device__ __align__(16) float g_projA[(size_t)RN*HID];          // x@Wp1^T+b_proj
__device__ __align__(16) float g_proj[(size_t)BAT*HID];
__device__ __align__(16) float g_sel[(size_t)BAT*HID];
__device__ __align__(16) float g_logits[(size_t)RN*VOC];
__device__ unsigned g_barCnt;

// ---------------- helpers ----------------
__device__ __forceinline__ unsigned su32(const void* p) {
    return (unsigned)__cvta_generic_to_shared(p);
}
__device__ __forceinline__ void cpa16(void* smem_dst, const void* gsrc) {
    asm volatile("cp.async.cg.shared.global [%0], [%1], 16;"
                 :: "r"(su32(smem_dst)), "l"(gsrc));
}
#define CPA_COMMIT() asm volatile("cp.async.commit_group;")
#define CPA_WAIT0()  asm volatile("cp.async.wait_group 0;" ::: "memory")
#define CPA_WAIT1()  asm volatile("cp.async.wait_group 1;" ::: "memory")

__device__ __forceinline__ void ldmx4(unsigned* r, unsigned a) {
    asm volatile("ldmatrix.sync.aligned.m8n8.x4.shared.b16 {%0,%1,%2,%3},[%4];"
                 : "=r"(r[0]), "=r"(r[1]), "=r"(r[2]), "=r"(r[3]) : "r"(a));
}
__device__ __forceinline__ void ldmx2(unsigned* r, unsigned a) {
    asm volatile("ldmatrix.sync.aligned.m8n8.x2.shared.b16 {%0,%1},[%2];"
                 : "=r"(r[0]), "=r"(r[1]) : "r"(a));
}
__device__ __forceinline__ void mma16816(float* c, const unsigned* a, const unsigned* b) {
    asm volatile(
        "mma.sync.aligned.m16n8k16.row.col.f32.bf16.bf16.f32 "
        "{%0,%1,%2,%3},{%4,%5,%6,%7},{%8,%9},{%0,%1,%2,%3};"
        : "+f"(c[0]), "+f"(c[1]), "+f"(c[2]), "+f"(c[3])
        : "r"(a[0]), "r"(a[1]), "r"(a[2]), "r"(a[3]), "r"(b[0]), "r"(b[1]));
}
__device__ __forceinline__ uint32_t f2tf(float f) {
    uint32_t r;
    asm("cvt.rna.tf32.f32 %0, %1;" : "=r"(r) : "f"(f));
    return r;
}
__device__ __forceinline__ void mma1688tf(float* c, const uint32_t* a, const uint32_t* b) {
    asm volatile(
        "mma.sync.aligned.m16n8k8.row.col.f32.tf32.tf32.f32 "
        "{%0,%1,%2,%3},{%4,%5,%6,%7},{%8,%9},{%0,%1,%2,%3};"
        : "+f"(c[0]), "+f"(c[1]), "+f"(c[2]), "+f"(c[3])
        : "r"(a[0]), "r"(a[1]), "r"(a[2]), "r"(a[3]), "r"(b[0]), "r"(b[1]));
}

// ---------------- grid barrier (monotonic counter) ----------------
__device__ __forceinline__ unsigned ldacq(const unsigned* p) {
    unsigned v;
    asm volatile("ld.acquire.gpu.global.u32 %0, [%1];" : "=r"(v) : "l"(p));
    return v;
}
__device__ __forceinline__ void gsync(unsigned &target) {
    __syncthreads();
    if (threadIdx.x == 0) {
        __threadfence();
        atomicAdd(&g_barCnt, 1u);
        target += NBLK;
        while (ldacq(&g_barCnt) < target) { }
    }
    __syncthreads();
}

// ---------------- prep kernels ----------------
__global__ void k_prepA(const float* __restrict__ W_out, const float* __restrict__ W_ih,
                        const float* __restrict__ W_hh, const float* __restrict__ W_proj,
                        const float* __restrict__ b_ih, const float* __restrict__ b_hh) {
    int blk = blockIdx.x, tid = threadIdx.x;
    if (blk < WOUTB) {
        size_t i = (size_t)blk * 256 + tid;
        g_Wout[i] = __float2bfloat16_rn(W_out[i]);
    } else if (blk < WOUTB + 12288) {
        int i = (blk - WOUTB) * 256 + tid;
        int srow = i >> 10, k = i & 1023;
        int g = srow >> 10, h = srow & 1023;
        g_Wih3[((size_t)(3*h + g) << 10) | k] = __float2bfloat16_rn(W_ih[i]);
    } else if (blk < WOUTB + 24576) {
        int i = (blk - WOUTB - 12288) * 256 + tid;
        int srow = i >> 10, k = i & 1023;
        int g = srow >> 10, h = srow & 1023;
        g_Whh3f[((size_t)(3*h + g) << 10) | k] = W_hh[i];
    } else if (blk < WOUTB + 24576 + 4096) {
        int i = (blk - WOUTB - 24576) * 256 + tid;
        int j = i >> 10, k = i & 1023;
        g_Wp1[i]  = __float2bfloat16_rn(W_proj[(size_t)j * 2048 + k]);
        g_Wp2f[i] = W_proj[(size_t)j * 2048 + 1024 + k];
    } else {
        int i = (blk - WOUTB - 24576 - 4096) * 256 + tid;
        if (i < G3) {
            int g = i >> 10, h = i & 1023;
            g_bih3[3*h + g] = b_ih[i];
            g_bhh3[3*h + g] = b_hh[i];
        }
    }
}
__global__ void k_prepB(const int* __restrict__ input, const float* __restrict__ emb,
                        const float* __restrict__ memory) {
    int blk = blockIdx.x, tid = threadIdx.x;
    if (blk == 0 && tid == 0) g_barCnt = 0;
    if (blk < 8192) {
        int idx = blk * 256 + tid;
        int r = idx >> 10, h = idx & 1023;
        int t = r >> 5, b = r & 31;
        int tok = input[b * TN + t];
        float v = emb[(size_t)tok * HID + h];
        g_xbf[idx] = __float2bfloat16_rn(v > 0.f ? v : 0.f);
    } else {
        int idx = (blk - 8192) * 256 + tid;
        int k = idx >> 15, rest = idx & 32767;
        float v = memory[(size_t)(31 - k) * SLOT + rest];
        g_S[idx] = v;
        g_Sbf[idx] = __float2bfloat16_rn(v);
    }
}

// ---------------- bf16 128x128 GEMM body, cp.async 2-stage pipelined ----------------
__device__ __forceinline__ void gemm_prefetch(
    const __nv_bfloat16* A, const __nv_bfloat16* Wt, int m0, int n0, int k0,
    __nv_bfloat16 (*As)[40], __nv_bfloat16 (*Bs)[40], int tid)
{
#pragma unroll
    for (int v = 0; v < 2; v++) {
        int task = tid + v * 256;
        int row = task >> 2, seg = task & 3;
        cpa16(&As[row][seg * 8], &A [(size_t)(m0 + row) * 1024 + k0 + seg * 8]);
        cpa16(&Bs[row][seg * 8], &Wt[(size_t)(n0 + row) * 1024 + k0 + seg * 8]);
    }
    CPA_COMMIT();
}

__device__ __forceinline__ void gemm128_body(
    const __nv_bfloat16* __restrict__ A, const __nv_bfloat16* __restrict__ Wt,
    const float* __restrict__ bias, float* __restrict__ C, int N, int m0, int n0,
    __nv_bfloat16 (*As2)[128][40], __nv_bfloat16 (*Bs2)[128][40])
{
    const int tid = threadIdx.x, lane = tid & 31, wid = tid >> 5;
    const int wm = (wid & 1) * 64;
    const int wn = (wid >> 1) * 32;
    float acc[4][4][4] = {};

    gemm_prefetch(A, Wt, m0, n0, 0, As2[0], Bs2[0], tid);
    for (int it = 0; it < 32; it++) {
        CPA_WAIT0();
        __syncthreads();
        if (it < 31)
            gemm_prefetch(A, Wt, m0, n0, (it + 1) * 32, As2[(it + 1) & 1], Bs2[(it + 1) & 1], tid);
        __nv_bfloat16 (*As)[40] = As2[it & 1];
        __nv_bfloat16 (*Bs)[40] = Bs2[it & 1];
#pragma unroll
        for (int kk = 0; kk < 32; kk += 16) {
            unsigned af[4][4], bfm[4][2];
#pragma unroll
            for (int mi = 0; mi < 4; mi++)
                ldmx4(af[mi], su32(&As[wm + mi * 16 + (lane & 15)][kk + (lane >> 4) * 8]));
#pragma unroll
            for (int ni = 0; ni < 4; ni++)
                ldmx2(bfm[ni], su32(&Bs[wn + ni * 8 + (lane & 7)][kk + ((lane >> 3) & 1) * 8]));
#pragma unroll
            for (int mi = 0; mi < 4; mi++)
#pragma unroll
                for (int ni = 0; ni < 4; ni++)
                    mma16816(acc[mi][ni], af[mi], bfm[ni]);
        }
    }
#pragma unroll
    for (int mi = 0; mi < 4; mi++)
#pragma unroll
        for (int ni = 0; ni < 4; ni++) {
            int row = m0 + wm + mi * 16 + (lane >> 2);
            int col = n0 + wn + ni * 8 + (lane & 3) * 2;
            float b0 = bias[col], b1 = bias[col + 1];
            C[(size_t)row * N + col]           = acc[mi][ni][0] + b0;
            C[(size_t)row * N + col + 1]       = acc[mi][ni][1] + b1;
            C[(size_t)(row + 8) * N + col]     = acc[mi][ni][2] + b0;
            C[(size_t)(row + 8) * N + col + 1] = acc[mi][ni][3] + b1;
        }
}

// gi (y<24) + projA (y>=24) in one launch
__global__ __launch_bounds__(256) void k_gemm_all(const float* __restrict__ b_proj)
{
    __shared__ __align__(16) __nv_bfloat16 As2[2][128][40];
    __shared__ __align__(16) __nv_bfloat16 Bs2[2][128][40];
    int m0 = blockIdx.x * 128;
    if (blockIdx.y < 24)
        gemm128_body(g_xbf, g_Wih3, g_bih3, g_giAll, G3, m0, blockIdx.y * 128, As2, Bs2);
    else
        gemm128_body(g_xbf, g_Wp1, b_proj, g_projA, HID, m0, (blockIdx.y - 24) * 128, As2, Bs2);
}
// vocab projection — proven 128x128 multi-block-per-SM config
__global__ __launch_bounds__(256) void k_gemm_voc(const float* __restrict__ b_out)
{
    __shared__ __align__(16) __nv_bfloat16 As2[2][128][40];
    __shared__ __align__(16) __nv_bfloat16 Bs2[2][128][40];
    gemm128_body(g_Sbf + (size_t)MEMN * SLOT, g_Wout, b_out, g_logits, VOC,
                 blockIdx.x * 128, blockIdx.y * 128, As2, Bs2);
}

// ---------------- persistent recurrence kernel ----------------
// smem: wWp2[8][1028] | wWhh[24][1028] (tf32) | AsF[3][32][132] (f32) | red[8*32*24] | dots[32]
#define SM_RECUR ((8*1028 + 24*1028 + 3*32*132) * 4 + 8*32*24*4 + 128)
#define ABUF (32*132)

__global__ __launch_bounds__(256, 1) void k_recur()
{
    extern __shared__ __align__(16) char sm_raw[];
    uint32_t* wWp2 = (uint32_t*)sm_raw;
    uint32_t* wWhh = wWp2 + 8 * 1028;
    float*    AsF  = (float*)(wWhh + 24 * 1028);   // [3][32][132] raw f32 staging
    float*    red  = AsF + 3 * ABUF;               // [8][32][24]
    float*    dots = red + 8 * 32 * 24;            // [32]

    const int tid = threadIdx.x, blk = blockIdx.x;
    const int lane = tid & 31, wid = tid >> 5;
    const int r4 = lane >> 2, c4 = lane & 3;
    const int n0p = blk * 8, n0g = blk * 24, h0 = blk * 8;

    // cache weight slices as tf32 in smem (once)
    for (int i = tid; i < 8 * 1024; i += 256) {
        int r = i >> 10, k = i & 1023;
        wWp2[r * 1028 + k] = f2tf(g_Wp2f[(size_t)(n0p + r) * 1024 + k]);
    }
    for (int i = tid; i < 24 * 1024; i += 256) {
        int r = i >> 10, k = i & 1023;
        wWhh[r * 1028 + k] = f2tf(g_Whh3f[(size_t)(n0g + r) * 1024 + k]);
    }
    __syncthreads();

    unsigned target = 0;

    for (int t = 0; t < TN; t++) {
        // ===== phase P: proj(32x1024) = mem0 @ Wp2^T + projA[t], 8 cols/block =====
        {
            const float* Ap = g_S + (size_t)(t + 31) * SLOT;
            float accP[2][4] = {};
            // prologue: issue chunks 0,1
#pragma unroll
            for (int s = 0; s < 2; s++) {
                float* buf = AsF + s * ABUF;
#pragma unroll
                for (int v = 0; v < 4; v++) {
                    int task = tid + v * 256, row = task >> 5, seg = task & 31;
                    cpa16(&buf[row * 132 + seg * 4], &Ap[(size_t)row * 1024 + s * 128 + seg * 4]);
                }
                CPA_COMMIT();
            }
#pragma unroll 1
            for (int c = 0; c < 8; c++) {
                if (c < 7) CPA_WAIT1(); else CPA_WAIT0();
                __syncthreads();
                if (c + 2 < 8) {
                    float* buf = AsF + ((c + 2) % 3) * ABUF;
#pragma unroll
                    for (int v = 0; v < 4; v++) {
                        int task = tid + v * 256, row = task >> 5, seg = task & 31;
                        cpa16(&buf[row * 132 + seg * 4],
                              &Ap[(size_t)row * 1024 + (c + 2) * 128 + seg * 4]);
                    }
                    CPA_COMMIT();
                }
                const float* buf = AsF + (c % 3) * ABUF;
                int kb = wid * 16;
#pragma unroll
                for (int ks = 0; ks < 16; ks += 8) {
                    int kl = kb + ks, kg = c * 128 + kl;
                    uint32_t af[2][4], bf2[2];
#pragma unroll
                    for (int mi = 0; mi < 2; mi++) {
                        af[mi][0] = f2tf(buf[(mi * 16 + r4) * 132 + kl + c4]);
                        af[mi][1] = f2tf(buf[(mi * 16 + r4 + 8) * 132 + kl + c4]);
                        af[mi][2] = f2tf(buf[(mi * 16 + r4) * 132 + kl + c4 + 4]);
                        af[mi][3] = f2tf(buf[(mi * 16 + r4 + 8) * 132 + kl + c4 + 4]);
                    }
                    bf2[0] = wWp2[r4 * 1028 + kg + c4];
                    bf2[1] = wWp2[r4 * 1028 + kg + c4 + 4];
                    mma1688tf(accP[0], af[0], bf2);
                    mma1688tf(accP[1], af[1], bf2);
                }
            }
            {   // cross-warp partials
                float* pr = red + wid * 256;
                int cb = (lane & 3) * 2;
#pragma unroll
                for (int mi = 0; mi < 2; mi++) {
                    int rr = mi * 16 + r4;
                    pr[rr * 8 + cb]           = accP[mi][0];
                    pr[rr * 8 + cb + 1]       = accP[mi][1];
                    pr[(rr + 8) * 8 + cb]     = accP[mi][2];
                    pr[(rr + 8) * 8 + cb + 1] = accP[mi][3];
                }
            }
            __syncthreads();
            {
                int row = tid >> 3, col = tid & 7;
                float s = 0.f;
#pragma unroll
                for (int w = 0; w < 8; w++) s += red[w * 256 + row * 8 + col];
                s += g_projA[(size_t)t * SLOT + row * 1024 + n0p + col];
                g_proj[row * 1024 + n0p + col] = s;
            }
        }
        gsync(target);

        // ===== phase A: attention, blocks 0..31 (one per batch) =====
        if (blk < BAT) {
            const int b = blk;
            float* projS = AsF;
#pragma unroll
            for (int p = 0; p < 4; p++)
                projS[tid + p * 256] = __ldcg(&g_proj[b * HID + tid + p * 256]);
            __syncthreads();
#pragma unroll
            for (int s = 0; s < 4; s++) {
                int m = wid * 4 + s;
                const float* mrow = g_S + (size_t)(t + 31 - m) * SLOT + b * HID;
                float sum = 0.f;
#pragma unroll
                for (int j = 0; j < 32; j++)
                    sum += __ldcg(&mrow[lane + 32 * j]) * projS[lane + 32 * j];
#pragma unroll
                for (int o = 16; o; o >>= 1) sum += __shfl_xor_sync(~0u, sum, o);
                if (lane == 0) dots[m] = sum * 0.03125f;
            }
            __syncthreads();
            if (wid == 0) {
                float d = dots[lane], mx = d;
#pragma unroll
                for (int o = 16; o; o >>= 1) mx = fmaxf(mx, __shfl_xor_sync(~0u, mx, o));
                float e = expf(d - mx), ss = e;
#pragma unroll
                for (int o = 16; o; o >>= 1) ss += __shfl_xor_sync(~0u, ss, o);
                dots[lane] = e / ss;
            }
            __syncthreads();
#pragma unroll
            for (int p = 0; p < 4; p++) {
                int h = tid + p * 256;
                float acc = 0.f;
#pragma unroll
                for (int m = 0; m < 32; m++)
                    acc += dots[m] * __ldcg(&g_S[(size_t)(t + 31 - m) * SLOT + b * HID + h]);
                g_sel[b * HID + h] = acc;
            }
        }
        gsync(target);

        // ===== phase G: gh = sel @ Whh^T (24 gate-cols/block), gates, write h =====
        {
            float accG[2][3][4] = {};
#pragma unroll
            for (int s = 0; s < 2; s++) {
                float* buf = AsF + s * ABUF;
#pragma unroll
                for (int v = 0; v < 4; v++) {
                    int task = tid + v * 256, row = task >> 5, seg = task & 31;
                    cpa16(&buf[row * 132 + seg * 4], &g_sel[(size_t)row * 1024 + s * 128 + seg * 4]);
                }
                CPA_COMMIT();
            }
#pragma unroll 1
            for (int c = 0; c < 8; c++) {
                if (c < 7) CPA_WAIT1(); else CPA_WAIT0();
                __syncthreads();
                if (c + 2 < 8) {
                    float* buf = AsF + ((c + 2) % 3) * ABUF;
#pragma unroll
                    for (int v = 0; v < 4; v++) {
                        int task = tid + v * 256, row = task >> 5, seg = task & 31;
                        cpa16(&buf[row * 132 + seg * 4],
                              &g_sel[(size_t)row * 1024 + (c + 2) * 128 + seg * 4]);
                    }
                    CPA_COMMIT();
                }
                const float* buf = AsF + (c % 3) * ABUF;
                int kb = wid * 16;
#pragma unroll
                for (int ks = 0; ks < 16; ks += 8) {
                    int kl = kb + ks, kg = c * 128 + kl;
                    uint32_t af[2][4];
#pragma unroll
                    for (int mi = 0; mi < 2; mi++) {
                        af[mi][0] = f2tf(buf[(mi * 16 + r4) * 132 + kl + c4]);
                        af[mi][1] = f2tf(buf[(mi * 16 + r4 + 8) * 132 + kl + c4]);
                        af[mi][2] = f2tf(buf[(mi * 16 + r4) * 132 + kl + c4 + 4]);
                        af[mi][3] = f2tf(buf[(mi * 16 + r4 + 8) * 132 + kl + c4 + 4]);
                    }
#pragma unroll
                    for (int ni = 0; ni < 3; ni++) {
                        uint32_t bf2[2] = { wWhh[(ni * 8 + r4) * 1028 + kg + c4],
                                            wWhh[(ni * 8 + r4) * 1028 + kg + c4 + 4] };
                        mma1688tf(accG[0][ni], af[0], bf2);
                        mma1688tf(accG[1][ni], af[1], bf2);
                    }
                }
            }
            {
                float* pr = red + wid * 768;
                int cb = (lane & 3) * 2;
#pragma unroll
                for (int mi = 0; mi < 2; mi++)
#pragma unroll
                    for (int ni = 0; ni < 3; ni++) {
                        int rr = mi * 16 + r4, cc = ni * 8 + cb;
                        pr[rr * 24 + cc]           = accG[mi][ni][0];
                        pr[rr * 24 + cc + 1]       = accG[mi][ni][1];
                        pr[(rr + 8) * 24 + cc]     = accG[mi][ni][2];
                        pr[(rr + 8) * 24 + cc + 1] = accG[mi][ni][3];
                    }
            }
            __syncthreads();
            {
                int b = tid >> 3, hh = tid & 7;
                float gg[3];
#pragma unroll
                for (int g = 0; g < 3; g++) {
                    float s = g_bhh3[n0g + 3 * hh + g];
#pragma unroll
                    for (int w = 0; w < 8; w++) s += red[w * 768 + b * 24 + 3 * hh + g];
                    gg[g] = s;
                }
                const float* gi = g_giAll + (size_t)(t * BAT + b) * G3 + n0g + 3 * hh;
                float r = 1.f / (1.f + expf(-(gi[0] + gg[0])));
                float z = 1.f / (1.f + expf(-(gi[1] + gg[1])));
                float n = tanhf(gi[2] + r * gg[2]);
                float sv = __ldcg(&g_sel[b * HID + h0 + hh]);
                float hv = (1.f - z) * n + z * sv;
                size_t o = (size_t)(MEMN + t) * SLOT + b * HID + h0 + hh;
                g_S[o] = hv;
                g_Sbf[o] = __float2bfloat16_rn(hv);
            }
        }
        gsync(target);
    }
}

// ---------------- fused log-softmax + transposed write (online logsumexp) ----------------
__global__ __launch_bounds__(256) void k_lseout(float* __restrict__ out)
{
    const int r = blockIdx.x;            // r = t*BAT + b
    const int t = r >> 5, b = r & 31;
    const float* row = g_logits + (size_t)r * VOC;
    __shared__ float sm_m[8], sm_s[8], lse_sh;
    int tid = threadIdx.x, lane = tid & 31, wid = tid >> 5;

    float m = -1e30f, ssum = 0.f;
    for (int i = tid; i < VOC; i += 256) {
        float x = row[i];
        if (x > m) { ssum = ssum * expf(m - x) + 1.f; m = x; }
        else       { ssum += expf(x - m); }
    }
#pragma unroll
    for (int o = 16; o; o >>= 1) {
        float m2 = __shfl_xor_sync(~0u, m, o);
        float s2 = __shfl_xor_sync(~0u, ssum, o);
        float mn = fmaxf(m, m2);
        ssum = ssum * expf(m - mn) + s2 * expf(m2 - mn);
        m = mn;
    }
    if (lane == 0) { sm_m[wid] = m; sm_s[wid] = ssum; }
    __syncthreads();
    if (tid == 0) {
        float M = sm_m[0];
        for (int w = 1; w < 8; w++) M = fmaxf(M, sm_m[w]);
        float S = 0.f;
        for (int w = 0; w < 8; w++) S += sm_s[w] * expf(sm_m[w] - M);
        lse_sh = M + logf(S);
    }
    __syncthreads();
    float l = lse_sh;
    const float4* src = (const float4*)row;
    float4* dst = (float4*)(out + ((size_t)b * TN + t) * VOC);
    for (int i = tid; i < VOC / 4; i += 256) {
        float4 v = src[i];
        v.x -= l; v.y -= l; v.z -= l; v.w -= l;
        dst[i] = v;
    }
}

// out2 (MEM,B,H): out2[m][b][h] = S[95-m][b][h]
__global__ void k_outmem(float* __restrict__ out2)
{
    int idx = blockIdx.x * 256 + threadIdx.x;
    int m = idx / (SLOT / 4);
    int rest = idx % (SLOT / 4);
    const float4* src = (const float4*)(g_S + (size_t)(MEMN + TN - 1 - m) * SLOT);
    float4* dst = (float4*)(out2 + (size_t)m * SLOT);
    dst[rest] = src[rest];
}

// ---------------- launch ----------------
extern "C" void kernel_launch(void* const* d_in, const int* in_sizes, int n_in,
                              void* d_out, int out_size)
{
    const int*   input  = (const int*)  d_in[0];
    const float* memory = (const float*)d_in[1];
    const float* emb    = (const float*)d_in[2];
    const float* W_proj = (const float*)d_in[3];
    const float* b_proj = (const float*)d_in[4];
    const float* W_ih   = (const float*)d_in[5];
    const float* W_hh   = (const float*)d_in[6];
    const float* b_ih   = (const float*)d_in[7];
    const float* b_hh   = (const float*)d_in[8];
    const float* W_out  = (const float*)d_in[9];
    const float* b_out  = (const float*)d_in[10];
    float* out = (float*)d_out;

    cudaFuncSetAttribute(k_recur, cudaFuncAttributeMaxDynamicSharedMemorySize, SM_RECUR);

    k_prepA<<<WOUTB + 24576 + 4096 + 12, 256>>>(W_out, W_ih, W_hh, W_proj, b_ih, b_hh); // 1
    k_prepB<<<8192 + 4096, 256>>>(input, emb, memory);                                  // 2
    k_gemm_all<<<dim3(16, 32), 256>>>(b_proj);                                          // 3
    k_recur<<<NBLK, 256, SM_RECUR>>>();                                                 // 4
    k_outmem<<<(MEMN * SLOT / 4) / 256, 256>>>(out + (size_t)BAT * TN * VOC);           // 5
    k_gemm_voc<<<dim3(16, 250), 256>>>(b_out);                                          // 6
    k_lseout<<<RN, 256>>>(out);                                                         // 7
}